// round 10
// baseline (speedup 1.0000x reference)
#include <cuda_runtime.h>
#include <cstdint>

// ---------------------------------------------------------------------------
// Problem constants
//   x:  (B=32, S=2048, I=256)  fp32
//   h0: (1, 32, 256)   c0: (1, 32, 256)
//   W:  (512, 1024)  rows 0..255 = Wx, rows 256..511 = Wh
//   b:  (1024,)
//   out = concat( hs (32,2048,256), zeros(1,32,256), zeros(1,32,256) )
// ---------------------------------------------------------------------------

#define B_   32
#define S_   2048
#define H_   256
#define N4H  1024

// Scratch: P[b][s][n] = x[b,s,:] @ Wx + bias   (256 MB)
__device__ float g_P[(size_t)B_ * S_ * N4H];

// ---------------------------------------------------------------------------
// Init: zero the two trailing output tensors
// ---------------------------------------------------------------------------
__global__ void init_kernel(float* out, int out_size) {
    int i = blockIdx.x * blockDim.x + threadIdx.x;
    const int base = B_ * S_ * H_;            // 16,777,216
    int n = out_size - base;                  // 16,384
    if (i < n) out[base + i] = 0.0f;
}

// ---------------------------------------------------------------------------
// Kernel 1: P = X @ Wx + bias -> g_P[b][s][n]  (row-major, row r = b*S + s)
//   BM=128, BN=64, BK=16, 256 threads, 8x4 microtile
// ---------------------------------------------------------------------------
__global__ __launch_bounds__(256) void gemm_xw(const float* __restrict__ X,
                                               const float* __restrict__ W,
                                               const float* __restrict__ bias) {
    __shared__ float As[16][132];
    __shared__ float Bs[16][68];

    const int bn  = blockIdx.x;          // 0..15
    const int bm  = blockIdx.y;          // 0..511
    const int tid = threadIdx.x;
    const int tx  = tid & 15;
    const int ty  = tid >> 4;

    const int rowBase = bm * 128;
    const int colBase = bn * 64;

    float acc[8][4];
#pragma unroll
    for (int i = 0; i < 8; i++)
#pragma unroll
        for (int j = 0; j < 4; j++) acc[i][j] = 0.0f;

    for (int k0 = 0; k0 < 256; k0 += 16) {
#pragma unroll
        for (int it = 0; it < 2; it++) {
            int idx = tid + it * 256;
            int m   = idx >> 2;
            int kq  = (idx & 3) << 2;
            float4 v = *(const float4*)(X + (size_t)(rowBase + m) * 256 + k0 + kq);
            As[kq + 0][m] = v.x;
            As[kq + 1][m] = v.y;
            As[kq + 2][m] = v.z;
            As[kq + 3][m] = v.w;
        }
        {
            int kk = tid >> 4;
            int nq = (tid & 15) << 2;
            float4 v = *(const float4*)(W + (size_t)(k0 + kk) * N4H + colBase + nq);
            *(float4*)&Bs[kk][nq] = v;
        }
        __syncthreads();

#pragma unroll
        for (int k = 0; k < 16; k++) {
            float a[8], bb[4];
            *(float4*)&a[0] = *(const float4*)&As[k][ty * 8];
            *(float4*)&a[4] = *(const float4*)&As[k][ty * 8 + 4];
            *(float4*)&bb[0] = *(const float4*)&Bs[k][tx * 4];
#pragma unroll
            for (int i = 0; i < 8; i++)
#pragma unroll
                for (int j = 0; j < 4; j++) acc[i][j] += a[i] * bb[j];
        }
        __syncthreads();
    }

    float4 bv = *(const float4*)(bias + colBase + tx * 4);
#pragma unroll
    for (int i = 0; i < 8; i++) {
        int r = rowBase + ty * 8 + i;
        float4 o;
        o.x = acc[i][0] + bv.x;
        o.y = acc[i][1] + bv.y;
        o.z = acc[i][2] + bv.z;
        o.w = acc[i][3] + bv.w;
        *(float4*)(g_P + (size_t)r * N4H + colBase + tx * 4) = o;
    }
}

// ---------------------------------------------------------------------------
// Kernel 2: cluster-based persistent recurrent LSTM.
//   16 clusters x 8 CTAs. Cluster grp owns batches {2*grp, 2*grp+1}.
//   CTA rank j owns h-columns [32j, 32j+32) -> z-cols {g*256 + 32j + c}.
//   128 threads: warp = gate (0..3), lane = c (0..31).
//   h exchanged via DSMEM push (st.shared::cluster) + cluster barrier.
//   h double-buffered in smem; cell state lives in registers.
// ---------------------------------------------------------------------------
#define WS_F   (128 * 260)         // Wh slice floats
#define HROW   260
#define HBUF   (2 * HROW)          // one h buffer: 2 batches x 260
#define HS_F   (2 * HBUF)          // double buffered
#define ZS_F   (8 * 32)
#define HST_F  64
#define SMEM_F (WS_F + HS_F + ZS_F + HST_F)

__device__ __forceinline__ uint32_t smem_u32(const void* p) {
    uint32_t a;
    asm("{ .reg .u64 t; cvta.to.shared.u64 t, %1; cvt.u32.u64 %0, t; }"
        : "=r"(a) : "l"(p));
    return a;
}
__device__ __forceinline__ uint32_t mapa_rank(uint32_t addr, uint32_t rank) {
    uint32_t r;
    asm("mapa.shared::cluster.u32 %0, %1, %2;" : "=r"(r) : "r"(addr), "r"(rank));
    return r;
}

__global__ __launch_bounds__(128, 1) __cluster_dims__(8, 1, 1)
void lstm_rec(const float* __restrict__ h0,
              const float* __restrict__ c0,
              const float* __restrict__ W,
              float* __restrict__ out) {
    extern __shared__ float smem[];
    float* Ws     = smem;                       // [col(g*32+c)][k] stride 260
    float* hs     = smem + WS_F;                // [buf][bi][k] stride 260
    float* zs     = smem + WS_F + HS_F;         // [(g*2+bi)*32 + c]
    float* hstage = smem + WS_F + HS_F + ZS_F;  // [bi*32 + c]

    const int tid  = threadIdx.x;
    const int g    = tid >> 5;        // gate 0..3
    const int lane = tid & 31;        // c
    const int cta  = blockIdx.x;
    const int grp  = cta >> 3;        // cluster id 0..15
    const int j    = cta & 7;         // rank in cluster
    const int b0   = 2 * grp;
    const int b1   = 2 * grp + 1;
    const int colBase = 32 * j;
    const int zcol    = g * 256 + colBase + lane;

    // Precompute remote bases of hs[0] for all 8 cluster ranks
    uint32_t hs_local = smem_u32(hs);
    uint32_t rbase[8];
#pragma unroll
    for (int r = 0; r < 8; r++) rbase[r] = mapa_rank(hs_local, (uint32_t)r);

    // ---- stage Wh slice ----
    for (int idx = tid; idx < 128 * 256; idx += 128) {
        int k  = idx >> 7;
        int cc = idx & 127;
        int gg = cc >> 5;
        int c  = cc & 31;
        Ws[cc * HROW + k] = W[(size_t)(256 + k) * N4H + gg * 256 + colBase + c];
    }
    // ---- stage h0 into buffer 0 ----
    {
        int bi = tid >> 6;
        int kq = (tid & 63) << 2;
        float4 v = *(const float4*)(h0 + (b0 + bi) * H_ + kq);
        *(float4*)&hs[bi * HROW + kq] = v;
    }
    // ---- cell state in registers (threads 0..63) ----
    float creg = 0.0f;
    if (tid < 64) {
        int bi = tid >> 5;
        int c  = tid & 31;
        creg = c0[(b0 + bi) * H_ + colBase + c];
    }
    __syncthreads();

    // ---- P prefetch for t=0 ----
    float pa = __ldcg(&g_P[((size_t)b0 * S_ + 0) * N4H + zcol]);
    float pb = __ldcg(&g_P[((size_t)b1 * S_ + 0) * N4H + zcol]);

    // push-vector decomposition for the DSMEM broadcast (all 128 threads)
    const int prank = tid >> 4;           // 0..7: destination rank
    const int pq    = tid & 15;           // 0..15: which float4
    const int pbi   = pq >> 3;            // 0..1
    const int pc4   = (pq & 7) * 4;       // 0..28

    for (int t = 0; t < S_; t++) {
        const int cur = t & 1;
        const int nxt = cur ^ 1;

        // ---- prefetch P[t+1] (clamped; hidden under the whole step) ----
        int tn = (t + 1 < S_) ? (t + 1) : t;
        float pan = __ldcg(&g_P[((size_t)b0 * S_ + tn) * N4H + zcol]);
        float pbn = __ldcg(&g_P[((size_t)b1 * S_ + tn) * N4H + zcol]);

        // ---- dot: z[b] = h[b] . Wh[:,zcol] ----
        float a00 = 0.f, a01 = 0.f, a02 = 0.f, a03 = 0.f;
        float a10 = 0.f, a11 = 0.f, a12 = 0.f, a13 = 0.f;
        const float4* wp  = (const float4*)&Ws[(g * 32 + lane) * HROW];
        const float4* hp0 = (const float4*)&hs[cur * HBUF];
        const float4* hp1 = (const float4*)&hs[cur * HBUF + HROW];
#pragma unroll 8
        for (int q = 0; q < 64; q++) {
            float4 w  = wp[q];
            float4 x0 = hp0[q];
            float4 x1 = hp1[q];
            a00 += w.x * x0.x; a01 += w.y * x0.y;
            a02 += w.z * x0.z; a03 += w.w * x0.w;
            a10 += w.x * x1.x; a11 += w.y * x1.y;
            a12 += w.z * x1.z; a13 += w.w * x1.w;
        }
        float pre0 = (a00 + a01) + (a02 + a03) + pa;
        float pre1 = (a10 + a11) + (a12 + a13) + pb;
        zs[(g * 2 + 0) * 32 + lane] = tanhf(pre0);
        zs[(g * 2 + 1) * 32 + lane] = tanhf(pre1);
        pa = pan; pb = pbn;
        __syncthreads();

        // ---- gate combine + cell/h update (threads 0..63) ----
        if (tid < 64) {
            int bi = tid >> 5;
            int c  = tid & 31;
            float zi = zs[(0 * 2 + bi) * 32 + c];
            float zf = zs[(1 * 2 + bi) * 32 + c];
            float zg = zs[(2 * 2 + bi) * 32 + c];
            float zo = zs[(3 * 2 + bi) * 32 + c];
            float ig = 1.0f / (1.0f + __expf(-zi));
            float fg = 1.0f / (1.0f + __expf(-zf));
            float gg = tanhf(zg);
            float og = 1.0f / (1.0f + __expf(-zo));
            float cv = fg * creg + ig * gg;
            creg = cv;
            float hn = tanhf(cv) * og;
            out[((size_t)(b0 + bi) * S_ + t) * H_ + colBase + c] = hn;
            hstage[bi * 32 + c] = hn;
        }
        __syncthreads();

        // ---- DSMEM broadcast: push our 64 h values to all 8 ranks ----
        {
            float4 v = *(const float4*)&hstage[pq * 4];
            uint32_t daddr = rbase[prank] +
                (uint32_t)((nxt * HBUF + pbi * HROW + colBase + pc4) * 4);
            asm volatile("st.shared::cluster.v4.f32 [%0], {%1,%2,%3,%4};"
                         :: "r"(daddr), "f"(v.x), "f"(v.y), "f"(v.z), "f"(v.w)
                         : "memory");
        }

        // ---- cluster barrier: release our pushes / acquire peers' ----
        asm volatile("barrier.cluster.arrive.aligned;" ::: "memory");
        asm volatile("barrier.cluster.wait.aligned;" ::: "memory");
    }
}

// ---------------------------------------------------------------------------
extern "C" void kernel_launch(void* const* d_in, const int* in_sizes, int n_in,
                              void* d_out, int out_size) {
    const float* x    = (const float*)d_in[0];
    const float* h0   = (const float*)d_in[1];
    const float* c0   = (const float*)d_in[2];
    const float* W    = (const float*)d_in[3];
    const float* bias = (const float*)d_in[4];
    float* out = (float*)d_out;

    cudaFuncSetAttribute(lstm_rec, cudaFuncAttributeMaxDynamicSharedMemorySize,
                         SMEM_F * (int)sizeof(float));

    init_kernel<<<64, 256>>>(out, out_size);

    dim3 ggrid(16, 512);
    gemm_xw<<<ggrid, 256>>>(x, W, bias);

    lstm_rec<<<128, 128, SMEM_F * sizeof(float)>>>(h0, c0, W, out);
}

// round 17
// speedup vs baseline: 1.2979x; 1.2979x over previous
#include <cuda_runtime.h>
#include <cstdint>

// ---------------------------------------------------------------------------
// Problem constants
//   x:  (B=32, S=2048, I=256)  fp32
//   h0: (1, 32, 256)   c0: (1, 32, 256)
//   W:  (512, 1024)  rows 0..255 = Wx, rows 256..511 = Wh
//   b:  (1024,)
//   out = concat( hs (32,2048,256), zeros(1,32,256), zeros(1,32,256) )
// ---------------------------------------------------------------------------

#define B_   32
#define S_   2048
#define H_   256
#define N4H  1024

// packed f32x2 FMA: acc = {acc.lo+x.lo*y.lo, acc.hi+x.hi*y.hi}
#define FMA2(acc, x, y) \
    asm volatile("fma.rn.f32x2 %0, %1, %2, %0;" : "+l"(acc) : "l"(x), "l"(y))
#define PACK2(d, lo, hi) \
    asm("mov.b64 %0, {%1, %2};" : "=l"(d) : "f"(lo), "f"(hi))
#define UNPACK2(lo, hi, s) \
    asm("mov.b64 {%0, %1}, %2;" : "=f"(lo), "=f"(hi) : "l"(s))

// Scratch: P[b][s][n] = x[b,s,:] @ Wx + bias   (256 MB)
__device__ float    g_P[(size_t)B_ * S_ * N4H];
// Double-buffered hidden state  g_h[buf][b][col]
__device__ float    g_h[2][B_ * H_];
// Per-(group,rank) step flags, padded 32B apart
__device__ unsigned g_flag[16 * 64];

// ---------------------------------------------------------------------------
// Init: reset flags, zero the two trailing output tensors
// ---------------------------------------------------------------------------
__global__ void init_kernel(float* out, int out_size) {
    int i = blockIdx.x * blockDim.x + threadIdx.x;
    if (i < 16 * 64) g_flag[i] = 0u;
    const int base = B_ * S_ * H_;            // 16,777,216
    int n = out_size - base;                  // 16,384
    if (i < n) out[base + i] = 0.0f;
}

// ---------------------------------------------------------------------------
// Kernel 1: P = X @ Wx + bias -> g_P[b][s][n]  (row-major, row r = b*S + s)
//   BM=128, BN=64, BK=16, 256 threads, 8x4 microtile, f32x2 packed FMA.
// ---------------------------------------------------------------------------
__global__ __launch_bounds__(256) void gemm_xw(const float* __restrict__ X,
                                               const float* __restrict__ W,
                                               const float* __restrict__ bias) {
    __shared__ __align__(16) float As[16][132];   // [k][m] transposed
    __shared__ __align__(16) float Bs[16][68];    // [k][n]

    const int bn  = blockIdx.x;          // 0..15
    const int bm  = blockIdx.y;          // 0..511
    const int tid = threadIdx.x;
    const int tx  = tid & 15;
    const int ty  = tid >> 4;

    const int rowBase = bm * 128;
    const int colBase = bn * 64;

    // acc2[p][j]: packed rows {2p,2p+1} x col j
    unsigned long long acc2[4][4];
#pragma unroll
    for (int p = 0; p < 4; p++)
#pragma unroll
        for (int j = 0; j < 4; j++) acc2[p][j] = 0ull;

    for (int k0 = 0; k0 < 256; k0 += 16) {
#pragma unroll
        for (int it = 0; it < 2; it++) {
            int idx = tid + it * 256;
            int m   = idx >> 2;
            int kq  = (idx & 3) << 2;
            float4 v = *(const float4*)(X + (size_t)(rowBase + m) * 256 + k0 + kq);
            As[kq + 0][m] = v.x;
            As[kq + 1][m] = v.y;
            As[kq + 2][m] = v.z;
            As[kq + 3][m] = v.w;
        }
        {
            int kk = tid >> 4;
            int nq = (tid & 15) << 2;
            float4 v = *(const float4*)(W + (size_t)(k0 + kk) * N4H + colBase + nq);
            *(float4*)&Bs[kk][nq] = v;
        }
        __syncthreads();

#pragma unroll
        for (int k = 0; k < 16; k++) {
            // a row-pairs: 8 consecutive m -> 4 packed b64
            ulonglong2 ap01 = *(const ulonglong2*)&As[k][ty * 8];
            ulonglong2 ap23 = *(const ulonglong2*)&As[k][ty * 8 + 4];
            float4 bv = *(const float4*)&Bs[k][tx * 4];
            unsigned long long bd0, bd1, bd2, bd3;
            PACK2(bd0, bv.x, bv.x);
            PACK2(bd1, bv.y, bv.y);
            PACK2(bd2, bv.z, bv.z);
            PACK2(bd3, bv.w, bv.w);
            FMA2(acc2[0][0], ap01.x, bd0); FMA2(acc2[0][1], ap01.x, bd1);
            FMA2(acc2[0][2], ap01.x, bd2); FMA2(acc2[0][3], ap01.x, bd3);
            FMA2(acc2[1][0], ap01.y, bd0); FMA2(acc2[1][1], ap01.y, bd1);
            FMA2(acc2[1][2], ap01.y, bd2); FMA2(acc2[1][3], ap01.y, bd3);
            FMA2(acc2[2][0], ap23.x, bd0); FMA2(acc2[2][1], ap23.x, bd1);
            FMA2(acc2[2][2], ap23.x, bd2); FMA2(acc2[2][3], ap23.x, bd3);
            FMA2(acc2[3][0], ap23.y, bd0); FMA2(acc2[3][1], ap23.y, bd1);
            FMA2(acc2[3][2], ap23.y, bd2); FMA2(acc2[3][3], ap23.y, bd3);
        }
        __syncthreads();
    }

    float4 bv = *(const float4*)(bias + colBase + tx * 4);
#pragma unroll
    for (int p = 0; p < 4; p++) {
        float lo0, hi0, lo1, hi1, lo2, hi2, lo3, hi3;
        UNPACK2(lo0, hi0, acc2[p][0]);
        UNPACK2(lo1, hi1, acc2[p][1]);
        UNPACK2(lo2, hi2, acc2[p][2]);
        UNPACK2(lo3, hi3, acc2[p][3]);
        int r0 = rowBase + ty * 8 + 2 * p;
        float4 o0, o1;
        o0.x = lo0 + bv.x; o0.y = lo1 + bv.y; o0.z = lo2 + bv.z; o0.w = lo3 + bv.w;
        o1.x = hi0 + bv.x; o1.y = hi1 + bv.y; o1.z = hi2 + bv.z; o1.w = hi3 + bv.w;
        *(float4*)(g_P + (size_t)r0 * N4H + colBase + tx * 4)       = o0;
        *(float4*)(g_P + (size_t)(r0 + 1) * N4H + colBase + tx * 4) = o1;
    }
}

// ---------------------------------------------------------------------------
// Kernel 2: batch-partitioned persistent recurrent LSTM.
//   128 CTAs = 16 groups x 8. Group grp owns batches {2*grp, 2*grp+1}.
//   CTA j owns h-columns [32j, 32j+32) -> z-cols {g*256 + 32j + c}.
//   256 threads: m = tid>>7 (K half), g = (tid>>5)&3 (gate), lane = c.
//   Wh held in REGISTERS (64 packed f32x2 per thread); dot via fma.rn.f32x2.
//   Sync: per-CTA step flag, st.release / ld.acquire through L2.
// ---------------------------------------------------------------------------
__global__ __launch_bounds__(256, 1) void lstm_rec(const float* __restrict__ h0,
                                                   const float* __restrict__ c0,
                                                   const float* __restrict__ W,
                                                   float* __restrict__ out) {
    __shared__ __align__(16) float hs[4 * 260];   // [buf*2+bi][k] stride 260
    __shared__ float zsp[16 * 32];                // [(m*8+g*2+bi)*32 + c]

    const int tid  = threadIdx.x;
    const int m    = tid >> 7;        // K half: 0 -> k<128, 1 -> k>=128
    const int sub  = tid & 127;
    const int g    = sub >> 5;        // gate 0..3
    const int lane = sub & 31;        // c
    const int cta  = blockIdx.x;
    const int grp  = cta >> 3;        // 0..15
    const int j    = cta & 7;         // 0..7
    const int b0   = 2 * grp;
    const int b1   = 2 * grp + 1;
    const int colBase = 32 * j;
    const int zcol    = g * 256 + colBase + lane;

    // ---- Wh slice into registers: 128 k-values as 64 packed pairs ----
    unsigned long long wq[64];
    {
        const float* Wh = W + (size_t)(256 + m * 128) * N4H + zcol;
#pragma unroll
        for (int p = 0; p < 64; p++) {
            float w0 = Wh[(size_t)(2 * p) * N4H];
            float w1 = Wh[(size_t)(2 * p + 1) * N4H];
            PACK2(wq[p], w0, w1);
        }
    }

    // ---- stage h0 into buffer 0 ----
    if (tid < 128) {
        int bi = tid >> 6;
        int kq = (tid & 63) << 2;
        float4 v = *(const float4*)(h0 + (b0 + bi) * H_ + kq);
        *(float4*)&hs[(0 * 2 + bi) * 260 + kq] = v;
    }
    // ---- cell state in registers (threads 0..63) ----
    float creg = 0.0f;
    if (tid < 64) {
        int bi = tid >> 5;
        int c  = tid & 31;
        creg = c0[(b0 + bi) * H_ + colBase + c];
    }
    __syncthreads();

    // ---- P prefetch for t=0 (m==0 half only) ----
    float pa = 0.f, pb = 0.f;
    if (m == 0) {
        pa = __ldcg(&g_P[((size_t)b0 * S_) * N4H + zcol]);
        pb = __ldcg(&g_P[((size_t)b1 * S_) * N4H + zcol]);
    }

    for (int t = 0; t < S_; t++) {
        const int cur = t & 1;
        const int nxt = cur ^ 1;

        // ---- prefetch P[t+1] ----
        int tn = (t + 1 < S_) ? (t + 1) : t;
        float pan = 0.f, pbn = 0.f;
        if (m == 0) {
            pan = __ldcg(&g_P[((size_t)b0 * S_ + tn) * N4H + zcol]);
            pbn = __ldcg(&g_P[((size_t)b1 * S_ + tn) * N4H + zcol]);
        }

        // ---- packed dot over this thread's K half (k in [m*128, m*128+128)) ----
        // NOTE: ulonglong2 = 4 floats -> half offset is m*32 elements (m*128 floats).
        unsigned long long a00 = 0ull, a01 = 0ull, a10 = 0ull, a11 = 0ull;
        const ulonglong2* h0p = (const ulonglong2*)&hs[(cur * 2 + 0) * 260] + m * 32;
        const ulonglong2* h1p = (const ulonglong2*)&hs[(cur * 2 + 1) * 260] + m * 32;
#pragma unroll
        for (int q = 0; q < 16; q++) {
            ulonglong2 x0 = h0p[q];      // floats 4q..4q+3 of this half (broadcast)
            ulonglong2 x1 = h1p[q];
            FMA2(a00, wq[2 * q + 0], x0.x);
            FMA2(a01, wq[2 * q + 1], x0.y);
            FMA2(a10, wq[2 * q + 0], x1.x);
            FMA2(a11, wq[2 * q + 1], x1.y);
        }
        // second 64-float chunk of this half
        h0p += 16; h1p += 16;
#pragma unroll
        for (int q = 0; q < 16; q++) {
            ulonglong2 x0 = h0p[q];
            ulonglong2 x1 = h1p[q];
            FMA2(a00, wq[32 + 2 * q + 0], x0.x);
            FMA2(a01, wq[32 + 2 * q + 1], x0.y);
            FMA2(a10, wq[32 + 2 * q + 0], x1.x);
            FMA2(a11, wq[32 + 2 * q + 1], x1.y);
        }
        {
            float l0, h0f, l1, h1f, l2, h2f, l3, h3f;
            UNPACK2(l0, h0f, a00); UNPACK2(l1, h1f, a01);
            UNPACK2(l2, h2f, a10); UNPACK2(l3, h3f, a11);
            float d0 = ((l0 + h0f) + (l1 + h1f)) + pa;   // batch b0 partial
            float d1 = ((l2 + h2f) + (l3 + h3f)) + pb;   // batch b1 partial
            zsp[(m * 8 + g * 2 + 0) * 32 + lane] = d0;
            zsp[(m * 8 + g * 2 + 1) * 32 + lane] = d1;
        }
        pa = pan; pb = pbn;
        __syncthreads();

        // ---- gate combine + cell/h update (threads 0..63) ----
        if (tid < 64) {
            int bi = tid >> 5;
            int c  = tid & 31;
            float zi = zsp[(0 * 2 + bi) * 32 + c] + zsp[(8 + 0 * 2 + bi) * 32 + c];
            float zf = zsp[(1 * 2 + bi) * 32 + c] + zsp[(8 + 1 * 2 + bi) * 32 + c];
            float zg = zsp[(2 * 2 + bi) * 32 + c] + zsp[(8 + 2 * 2 + bi) * 32 + c];
            float zo = zsp[(3 * 2 + bi) * 32 + c] + zsp[(8 + 3 * 2 + bi) * 32 + c];
            zi = tanhf(zi); zf = tanhf(zf); zg = tanhf(zg); zo = tanhf(zo);
            float ig = 1.0f / (1.0f + __expf(-zi));
            float fg = 1.0f / (1.0f + __expf(-zf));
            float gg = tanhf(zg);
            float og = 1.0f / (1.0f + __expf(-zo));
            float cv = fg * creg + ig * gg;
            creg = cv;
            float hn = tanhf(cv) * og;
            out[((size_t)(b0 + bi) * S_ + t) * H_ + colBase + c] = hn;
            __stcg(&g_h[nxt][(b0 + bi) * H_ + colBase + c], hn);
        }
        __syncthreads();   // order h stores before the release flag (cumulativity)

        if (t + 1 < S_) {
            // ---- publish: release-store our step flag ----
            if (tid == 0) {
                unsigned v = (unsigned)(t + 1);
                asm volatile("st.release.gpu.global.u32 [%0], %1;"
                             :: "l"(&g_flag[grp * 64 + j * 8]), "r"(v) : "memory");
            }
            // ---- consume: each loader thread waits only for ITS producer ----
            if (tid < 128) {
                int bi   = tid >> 6;
                int kq   = (tid & 63) << 2;
                int jsrc = (tid & 63) >> 3;            // producer of cols [kq, kq+4)
                const unsigned* fp = &g_flag[grp * 64 + jsrc * 8];
                unsigned v;
                do {
                    asm volatile("ld.acquire.gpu.global.u32 %0, [%1];"
                                 : "=r"(v) : "l"(fp) : "memory");
                } while (v < (unsigned)(t + 1));
                float4 hv = __ldcg((const float4*)&g_h[nxt][(b0 + bi) * H_ + kq]);
                *(float4*)&hs[(nxt * 2 + bi) * 260 + kq] = hv;
            }
            __syncthreads();
        }
    }
}

// ---------------------------------------------------------------------------
extern "C" void kernel_launch(void* const* d_in, const int* in_sizes, int n_in,
                              void* d_out, int out_size) {
    const float* x    = (const float*)d_in[0];
    const float* h0   = (const float*)d_in[1];
    const float* c0   = (const float*)d_in[2];
    const float* W    = (const float*)d_in[3];
    const float* bias = (const float*)d_in[4];
    float* out = (float*)d_out;

    init_kernel<<<64, 256>>>(out, out_size);

    dim3 ggrid(16, 512);
    gemm_xw<<<ggrid, 256>>>(x, W, bias);

    lstm_rec<<<128, 256>>>(h0, c0, W, out);
}